// round 2
// baseline (speedup 1.0000x reference)
#include <cuda_runtime.h>
#include <math.h>

typedef unsigned long long ULL;

#define NB 2
#define NS 2048
#define NE 1024
#define NH 16
#define NHD 64
#define NM 4096                  // NB*NS
#define ATT_SCALE (1.0f/32.0f)   // 1/sqrt(1024), exact power of two

// ---------------- scratch (device globals; no allocation allowed) ----------
__device__ float g_q[NB*NH*NS*NHD];    // head-major: [b*16+h][s][hd]
__device__ float g_k[NB*NH*NS*NHD];
__device__ float g_v[NB*NH*NS*NHD];
__device__ float g_ctx[NB*NH*NS*NHD];
__device__ float g_cos[NS*32];
__device__ float g_sin[NS*32];

// ---------------- packed f32x2 helpers (Blackwell FFMA2 path) --------------
__device__ __forceinline__ ULL pk2(float lo, float hi){
    ULL r; unsigned a=__float_as_uint(lo), b=__float_as_uint(hi);
    asm("mov.b64 %0, {%1,%2};" : "=l"(r) : "r"(a), "r"(b));
    return r;
}
__device__ __forceinline__ void up2(ULL v, float& lo, float& hi){
    unsigned a,b;
    asm("mov.b64 {%0,%1}, %2;" : "=r"(a), "=r"(b) : "l"(v));
    lo=__uint_as_float(a); hi=__uint_as_float(b);
}
__device__ __forceinline__ void fma2(ULL& d, ULL a, ULL b){
    asm("fma.rn.f32x2 %0, %1, %2, %0;" : "+l"(d) : "l"(a), "l"(b));
}
__device__ __forceinline__ ULL mul2(ULL a, ULL b){
    ULL d; asm("mul.rn.f32x2 %0, %1, %2;" : "=l"(d) : "l"(a), "l"(b));
    return d;
}

// ---------------- GEMM: C[m,n] = sum_e A[m,e] * W[n,e]  (NT) ---------------
// M=4096, N=1024, K=1024. Tile 128x128, BK=16, 256 threads, 8x8 per thread.
// a_heads: read A from head-major layout. c_heads: write C to head-major.
__global__ void __launch_bounds__(256, 2)
gemm_nt(const float* __restrict__ A, const float* __restrict__ Wt,
        float* __restrict__ C, int a_heads, int c_heads)
{
    __shared__ __align__(16) float As[16][128];
    __shared__ __align__(16) float Bs[16][128];
    const int t  = threadIdx.x;
    const int tx = t & 15;          // 16 col groups (8 cols each)
    const int ty = t >> 4;          // 16 row groups (8 rows each)
    const int bm = blockIdx.y * 128;
    const int bn = blockIdx.x * 128;

    ULL acc[4][8];                  // [row-pair][col]
    #pragma unroll
    for (int i=0;i<4;++i)
        #pragma unroll
        for (int j=0;j<8;++j) acc[i][j] = 0ULL;

    for (int kt = 0; kt < 64; ++kt) {
        const int k0 = kt * 16;
        #pragma unroll
        for (int it = 0; it < 2; ++it) {
            int i4  = it*256 + t;           // 512 float4 per tile
            int row = i4 >> 2, c4 = i4 & 3;
            int m = bm + row, e = k0 + c4*4;
            const float* srcA;
            if (!a_heads) srcA = A + (size_t)m*NE + e;
            else {
                int b = m >> 11, s = m & 2047, h = e >> 6, hd = e & 63;
                srcA = A + ((size_t)((b*16 + h)*NS + s))*64 + hd;
            }
            float4 fa = *(const float4*)srcA;
            As[c4*4+0][row]=fa.x; As[c4*4+1][row]=fa.y;
            As[c4*4+2][row]=fa.z; As[c4*4+3][row]=fa.w;
            float4 fb = *(const float4*)(Wt + (size_t)(bn+row)*NE + e);
            Bs[c4*4+0][row]=fb.x; Bs[c4*4+1][row]=fb.y;
            Bs[c4*4+2][row]=fb.z; Bs[c4*4+3][row]=fb.w;
        }
        __syncthreads();
        #pragma unroll
        for (int kk = 0; kk < 16; ++kk) {
            const ULL* Ap = (const ULL*)&As[kk][ty*8];
            ULL a0=Ap[0], a1=Ap[1], a2=Ap[2], a3=Ap[3];
            float4 b0 = *(const float4*)&Bs[kk][tx*8];
            float4 b1 = *(const float4*)&Bs[kk][tx*8+4];
            float bb[8] = {b0.x,b0.y,b0.z,b0.w,b1.x,b1.y,b1.z,b1.w};
            #pragma unroll
            for (int j=0;j<8;++j){
                ULL b2 = pk2(bb[j], bb[j]);
                fma2(acc[0][j], a0, b2);
                fma2(acc[1][j], a1, b2);
                fma2(acc[2][j], a2, b2);
                fma2(acc[3][j], a3, b2);
            }
        }
        __syncthreads();
    }
    #pragma unroll
    for (int i=0;i<4;++i) {
        float lo[8], hi[8];
        #pragma unroll
        for (int j=0;j<8;++j) up2(acc[i][j], lo[j], hi[j]);
        #pragma unroll
        for (int l=0;l<2;++l) {
            float* o = l ? hi : lo;
            int m = bm + ty*8 + 2*i + l;
            float4 f0 = make_float4(o[0],o[1],o[2],o[3]);
            float4 f1 = make_float4(o[4],o[5],o[6],o[7]);
            if (!c_heads) {
                float* dst = C + (size_t)m*NE + bn + tx*8;
                *(float4*)dst = f0;  *(float4*)(dst+4) = f1;
            } else {
                int b = m >> 11, s = m & 2047;
                int n0 = bn + tx*8;
                *(float4*)(C + ((size_t)((b*16+(n0>>6))*NS+s))*64 + (n0&63)) = f0;
                int n1 = n0 + 4;
                *(float4*)(C + ((size_t)((b*16+(n1>>6))*NS+s))*64 + (n1&63)) = f1;
            }
        }
    }
}

// ---------------- RoPE table + apply ---------------------------------------
__global__ void rope_table_kernel()
{
    int idx = blockIdx.x * blockDim.x + threadIdx.x;   // 65536
    if (idx >= NS*32) return;
    int s = idx >> 5, p = idx & 31;
    double invf = 1.0 / pow(10000.0, (double)(2*p) / 64.0);
    double a = (double)s * invf;
    g_cos[idx] = (float)cos(a);
    g_sin[idx] = (float)sin(a);
}

__global__ void rope_apply_kernel(float* __restrict__ x)
{
    int t = blockIdx.x * blockDim.x + threadIdx.x;     // pair index
    if (t >= NB*NH*NS*32) return;
    int sp = t & (NS*32 - 1);                          // s*32 + p (per bh)
    float c = g_cos[sp], s = g_sin[sp];
    float2 v = *(float2*)(x + (size_t)t*2);
    float2 o;
    o.x = v.x*c - v.y*s;
    o.y = v.x*s + v.y*c;
    *(float2*)(x + (size_t)t*2) = o;
}

// ---------------- Flash attention (fp32, shifted-causal mask) --------------
// Per block: one (bh, q-tile of 64). 128 threads; frag = 8 rows x 4 cols.
#define FL_SMEM_FLOATS (64*66 + 64*65 + 64*65 + 64*66)
#define FL_SMEM_BYTES  (FL_SMEM_FLOATS*4)

__global__ void __launch_bounds__(128, 3)
flash_attn_kernel()
{
    extern __shared__ __align__(16) float sm[];
    float* Qt = sm;                       // [d][r] stride 66 (Q^T, pre-scaled)
    float* Ks = Qt + 64*66;               // [c][d] stride 65
    float* Vs = Ks + 64*65;               // [c][d] stride 65
    float* Pt = Vs + 64*65;               // [c][r] stride 66

    const int t  = threadIdx.x;
    const int tx = t & 15;                // col group (4 cols)
    const int ty = t >> 4;                // row group (8 rows)
    const int bh = blockIdx.y;
    const int qb = (int)gridDim.x - 1 - (int)blockIdx.x;   // heavy tiles first
    const int q0 = qb * 64;

    const float* qp = g_q + (size_t)bh * NS * 64;
    const float* kp = g_k + (size_t)bh * NS * 64;
    const float* vp = g_v + (size_t)bh * NS * 64;

    #pragma unroll
    for (int it = 0; it < 8; ++it) {
        int i4  = it*128 + t;             // 1024 float4
        int row = i4 >> 4, c4 = i4 & 15;
        float4 f = *(const float4*)(qp + (size_t)(q0+row)*64 + c4*4);
        int d = c4*4;
        Qt[(d+0)*66 + row] = f.x * ATT_SCALE;
        Qt[(d+1)*66 + row] = f.y * ATT_SCALE;
        Qt[(d+2)*66 + row] = f.z * ATT_SCALE;
        Qt[(d+3)*66 + row] = f.w * ATT_SCALE;
    }

    float m_r[8], l_r[8];
    #pragma unroll
    for (int r=0;r<8;++r){ m_r[r] = -1e30f; l_r[r] = 0.0f; }
    ULL ctx2[4][4];                       // [row-pair][d-col]
    #pragma unroll
    for (int i=0;i<4;++i)
        #pragma unroll
        for (int j=0;j<4;++j) ctx2[i][j] = 0ULL;

    for (int kb = 0; kb <= qb; ++kb) {
        const int k0 = kb * 64;
        #pragma unroll
        for (int it = 0; it < 8; ++it) {
            int i4  = it*128 + t;
            int row = i4 >> 4, c4 = i4 & 15;
            float4 f = *(const float4*)(kp + (size_t)(k0+row)*64 + c4*4);
            float* kd = &Ks[row*65 + c4*4];
            kd[0]=f.x; kd[1]=f.y; kd[2]=f.z; kd[3]=f.w;
            float4 g = *(const float4*)(vp + (size_t)(k0+row)*64 + c4*4);
            float* vd = &Vs[row*65 + c4*4];
            vd[0]=g.x; vd[1]=g.y; vd[2]=g.z; vd[3]=g.w;
        }
        __syncthreads();

        // S = (Q*scale) @ K^T ; row-paired f32x2
        ULL s2[4][4];
        #pragma unroll
        for (int i=0;i<4;++i)
            #pragma unroll
            for (int c=0;c<4;++c) s2[i][c] = 0ULL;
        #pragma unroll 8
        for (int d = 0; d < 64; ++d) {
            const ULL* qq = (const ULL*)&Qt[d*66 + ty*8];
            ULL a0=qq[0], a1=qq[1], a2=qq[2], a3=qq[3];
            #pragma unroll
            for (int c=0;c<4;++c) {
                float kv = Ks[(tx*4+c)*65 + d];
                ULL k2 = pk2(kv, kv);
                fma2(s2[0][c], a0, k2);
                fma2(s2[1][c], a1, k2);
                fma2(s2[2][c], a2, k2);
                fma2(s2[3][c], a3, k2);
            }
        }

        // online softmax + write P^T
        #pragma unroll
        for (int i=0;i<4;++i) {
            float v_[2][4];
            #pragma unroll
            for (int c=0;c<4;++c) up2(s2[i][c], v_[0][c], v_[1][c]);
            float fac2[2];
            #pragma unroll
            for (int l=0;l<2;++l) {
                int r  = 2*i + l;
                int gi = q0 + ty*8 + r;
                float rm = -1e30f;
                #pragma unroll
                for (int c=0;c<4;++c) {
                    int gj = k0 + tx*4 + c;
                    float s = v_[l][c];
                    if (gj >= gi && !(gi == 0 && gj == 0)) s = -1e30f;
                    v_[l][c] = s;
                    rm = fmaxf(rm, s);
                }
                #pragma unroll
                for (int off=1; off<16; off<<=1)
                    rm = fmaxf(rm, __shfl_xor_sync(0xffffffffu, rm, off));
                float mnew = fmaxf(m_r[r], rm);
                float fac  = expf(m_r[r] - mnew);
                float ps = 0.0f;
                #pragma unroll
                for (int c=0;c<4;++c) {
                    float p = expf(v_[l][c] - mnew);
                    Pt[(tx*4+c)*66 + ty*8 + r] = p;
                    ps += p;
                }
                #pragma unroll
                for (int off=1; off<16; off<<=1)
                    ps += __shfl_xor_sync(0xffffffffu, ps, off);
                l_r[r] = l_r[r]*fac + ps;
                m_r[r] = mnew;
                fac2[l] = fac;
            }
            ULL ff = pk2(fac2[0], fac2[1]);
            #pragma unroll
            for (int j=0;j<4;++j) ctx2[i][j] = mul2(ctx2[i][j], ff);
        }
        __syncthreads();

        // ctx += P @ V ; row-paired f32x2
        #pragma unroll 8
        for (int c = 0; c < 64; ++c) {
            const ULL* pp = (const ULL*)&Pt[c*66 + ty*8];
            ULL p0=pp[0], p1=pp[1], p2=pp[2], p3=pp[3];
            #pragma unroll
            for (int j=0;j<4;++j) {
                float vv = Vs[c*65 + tx*4 + j];
                ULL v2 = pk2(vv, vv);
                fma2(ctx2[0][j], p0, v2);
                fma2(ctx2[1][j], p1, v2);
                fma2(ctx2[2][j], p2, v2);
                fma2(ctx2[3][j], p3, v2);
            }
        }
        __syncthreads();
    }

    // normalize + write ctx (head-major)
    float* op = g_ctx + (size_t)bh * NS * 64;
    #pragma unroll
    for (int i=0;i<4;++i) {
        float lo[4], hi[4];
        #pragma unroll
        for (int j=0;j<4;++j) up2(ctx2[i][j], lo[j], hi[j]);
        #pragma unroll
        for (int l=0;l<2;++l) {
            float* o = l ? hi : lo;
            int r = 2*i + l;
            float inv = 1.0f / l_r[r];
            float4 f = make_float4(o[0]*inv, o[1]*inv, o[2]*inv, o[3]*inv);
            *(float4*)(op + (size_t)(q0 + ty*8 + r)*64 + tx*4) = f;
        }
    }
}

// ---------------------------------------------------------------------------
extern "C" void kernel_launch(void* const* d_in, const int* in_sizes, int n_in,
                              void* d_out, int out_size)
{
    const float* q  = (const float*)d_in[0];
    const float* k  = (const float*)d_in[1];
    const float* v  = (const float*)d_in[2];
    const float* Wq = (const float*)d_in[3];
    const float* Wk = (const float*)d_in[4];
    const float* Wv = (const float*)d_in[5];
    const float* Wo = (const float*)d_in[6];
    float* out = (float*)d_out;

    float *pq, *pk, *pv, *pctx;
    cudaGetSymbolAddress((void**)&pq,   g_q);
    cudaGetSymbolAddress((void**)&pk,   g_k);
    cudaGetSymbolAddress((void**)&pv,   g_v);
    cudaGetSymbolAddress((void**)&pctx, g_ctx);

    cudaFuncSetAttribute(flash_attn_kernel,
                         cudaFuncAttributeMaxDynamicSharedMemorySize,
                         FL_SMEM_BYTES);

    rope_table_kernel<<<256, 256>>>();

    dim3 gg(NE/128, NM/128);               // (8, 32)
    gemm_nt<<<gg, 256>>>(q, Wq, pq, 0, 1);
    gemm_nt<<<gg, 256>>>(k, Wk, pk, 0, 1);
    gemm_nt<<<gg, 256>>>(v, Wv, pv, 0, 1);

    int npair = NB*NH*NS*32;
    rope_apply_kernel<<<(npair+255)/256, 256>>>(pq);
    rope_apply_kernel<<<(npair+255)/256, 256>>>(pk);

    dim3 fg(NS/64, NB*NH);                 // (32, 32)
    flash_attn_kernel<<<fg, 128, FL_SMEM_BYTES>>>();

    gemm_nt<<<gg, 256>>>(pctx, Wo, out, 1, 0);
}